// round 1
// baseline (speedup 1.0000x reference)
#include <cuda_runtime.h>
#include <cuda_bf16.h>
#include <math.h>

// Shapes (fixed per reference): B=2048, D=128, H=512
#define BATCH 2048
#define DDIM  128
#define HDIM  512

// ---------------- device scratch (static; no allocations) ----------------
__device__ float g_ench[BATCH * HDIM];           // 4 MB   leaky(x@We1^T+be1)
__device__ float g_enc [BATCH * DDIM];           // 1 MB   tanh(...@We2^T+be2)
__device__ float g_w2t [DDIM * HDIM * DDIM];     // 33.5MB W2s transposed to (j,h,d)

// ---------------- kernel 1: generic NT GEMM + bias + activation ----------
// C[m][n] = act( sum_k A[m][k] * Bw[n][k] + bias[n] )
// tiles: 64x64, K-chunk 32, 256 threads, thread tile 4x4.
// Requires M%64==0, N%64==0, K%32==0 (true for both encoder GEMMs).
__global__ void gemm_nt_bias_act(const float* __restrict__ A,
                                 const float* __restrict__ Bw,
                                 const float* __restrict__ bias,
                                 float* __restrict__ C,
                                 int M, int N, int K, int act)
{
    __shared__ __align__(16) float As[32][68];   // [k][m], 68 pad: row=272B (16B mult)
    __shared__ __align__(16) float Bs[32][68];   // [k][n]

    const int t  = threadIdx.x;            // 0..255
    const int m0 = blockIdx.x * 64;
    const int n0 = blockIdx.y * 64;
    const int mg = t >> 4;                 // 0..15
    const int ng = t & 15;                 // 0..15

    float acc[4][4] = {};

    for (int k0 = 0; k0 < K; k0 += 32) {
        __syncthreads();
#pragma unroll
        for (int i = 0; i < 8; i++) {
            int idx = i * 256 + t;
            int m = idx >> 5, k = idx & 31;
            As[k][m] = A [(size_t)(m0 + m) * K + k0 + k];
            Bs[k][m] = Bw[(size_t)(n0 + m) * K + k0 + k];
        }
        __syncthreads();
#pragma unroll
        for (int k = 0; k < 32; k++) {
            float4 av = *(const float4*)&As[k][mg * 4];
            float4 bv = *(const float4*)&Bs[k][ng * 4];
            acc[0][0] = fmaf(av.x, bv.x, acc[0][0]);
            acc[0][1] = fmaf(av.x, bv.y, acc[0][1]);
            acc[0][2] = fmaf(av.x, bv.z, acc[0][2]);
            acc[0][3] = fmaf(av.x, bv.w, acc[0][3]);
            acc[1][0] = fmaf(av.y, bv.x, acc[1][0]);
            acc[1][1] = fmaf(av.y, bv.y, acc[1][1]);
            acc[1][2] = fmaf(av.y, bv.z, acc[1][2]);
            acc[1][3] = fmaf(av.y, bv.w, acc[1][3]);
            acc[2][0] = fmaf(av.z, bv.x, acc[2][0]);
            acc[2][1] = fmaf(av.z, bv.y, acc[2][1]);
            acc[2][2] = fmaf(av.z, bv.z, acc[2][2]);
            acc[2][3] = fmaf(av.z, bv.w, acc[2][3]);
            acc[3][0] = fmaf(av.w, bv.x, acc[3][0]);
            acc[3][1] = fmaf(av.w, bv.y, acc[3][1]);
            acc[3][2] = fmaf(av.w, bv.z, acc[3][2]);
            acc[3][3] = fmaf(av.w, bv.w, acc[3][3]);
        }
    }

#pragma unroll
    for (int i = 0; i < 4; i++) {
        int m = m0 + mg * 4 + i;
#pragma unroll
        for (int j = 0; j < 4; j++) {
            int n = n0 + ng * 4 + j;
            float c = acc[i][j] + bias[n];
            c = (act == 0) ? fmaxf(c, 0.2f * c) : tanhf(c);
            C[(size_t)m * N + n] = c;
        }
    }
}

// ---------------- kernel 2: W2s (j,d,h) -> W2T (j,h,d) --------------------
// grid: (D/32, H/32, 128), block (32,8)
__global__ void transpose_w2(const float* __restrict__ W2s, float* __restrict__ W2T)
{
    __shared__ float s[32][33];
    const int j  = blockIdx.z;
    const int d0 = blockIdx.x * 32;
    const int h0 = blockIdx.y * 32;
    const int tx = threadIdx.x, ty = threadIdx.y;

    const float* src = W2s + (size_t)j * DDIM * HDIM;
    float*       dst = W2T + (size_t)j * HDIM * DDIM;

#pragma unroll
    for (int i = 0; i < 32; i += 8)
        s[ty + i][tx] = src[(size_t)(d0 + ty + i) * HDIM + h0 + tx];
    __syncthreads();
#pragma unroll
    for (int i = 0; i < 32; i += 8)
        dst[(size_t)(h0 + ty + i) * DDIM + d0 + tx] = s[tx][ty + i];
}

// ---------------- kernel 3: fused decoders + prefix-sum + tanh ------------
// Each CTA owns (BT=64 batch rows) x (DT=32 output dims), walks j = 0..127
// sequentially keeping the running cumsum in registers. Per j:
//   hid[h][b] = leaky(z[j,b]*W1s[j,h] + b1s[j,h])   (recomputed in SMEM)
//   acc[b][d] += sum_h hid[h][b] * W2T[j][h][d] + b2s[j][d]
//   out[j][b][d] = tanh(acc[b][d])
// grid (2048/64, 128/32) = (32,4) = 128 CTAs, 256 threads, thread tile 4b x 2d.
#define BT 64
#define DT 32
#define HC 64
__global__ __launch_bounds__(256, 1)
void decoder_kernel(const float* __restrict__ encoded,
                    const float* __restrict__ W1s,
                    const float* __restrict__ b1s,
                    const float* __restrict__ w2t,
                    const float* __restrict__ b2s,
                    float* __restrict__ out)
{
    __shared__ __align__(16) float hid_s[HC][BT];    // 16 KB
    __shared__ __align__(16) float w2_s [HC][DT];    // 8 KB
    __shared__ float w1_s[HDIM];                     // 2 KB
    __shared__ float b1_s[HDIM];                     // 2 KB
    __shared__ float z_s [BT];

    const int t  = threadIdx.x;           // 0..255
    const int b0 = blockIdx.x * BT;
    const int d0 = blockIdx.y * DT;
    const int bg = t >> 4;                // 0..15 -> 4 consecutive b
    const int dg = t & 15;                // 0..15 -> 2 consecutive d

    float acc[4][2] = {};                 // running cumsum

    for (int j = 0; j < DDIM; j++) {
        __syncthreads();  // protect w1/b1/z from previous iteration readers
        w1_s[t]       = W1s[(size_t)j * HDIM + t];
        w1_s[t + 256] = W1s[(size_t)j * HDIM + t + 256];
        b1_s[t]       = b1s[(size_t)j * HDIM + t];
        b1_s[t + 256] = b1s[(size_t)j * HDIM + t + 256];
        if (t < BT) z_s[t] = encoded[(size_t)(b0 + t) * DDIM + j];

        for (int hc = 0; hc < HDIM; hc += HC) {
            __syncthreads();  // prev chunk compute done (also covers w1/z fill)
            // fill hid chunk: 64h x 64b, 16 elems/thread, conflict-free stores
#pragma unroll
            for (int i = 0; i < 16; i++) {
                int idx = i * 256 + t;
                int h = idx >> 6, b = idx & 63;
                float v = fmaf(z_s[b], w1_s[hc + h], b1_s[hc + h]);
                hid_s[h][b] = fmaxf(v, 0.2f * v);
            }
            // load W2T chunk (j, hc..hc+63, d0..d0+31): coalesced, conflict-free
#pragma unroll
            for (int i = 0; i < 8; i++) {
                int idx = i * 256 + t;
                int h = idx >> 5, d = idx & 31;
                w2_s[h][d] = w2t[((size_t)j * HDIM + hc + h) * DDIM + d0 + d];
            }
            __syncthreads();
            // rank-update: per h: 1 LDS.128 + 1 LDS.64 + 8 FFMA
#pragma unroll
            for (int h = 0; h < HC; h++) {
                float4 hv = *(const float4*)&hid_s[h][bg * 4];
                float2 wv = *(const float2*)&w2_s[h][dg * 2];
                acc[0][0] = fmaf(hv.x, wv.x, acc[0][0]);
                acc[0][1] = fmaf(hv.x, wv.y, acc[0][1]);
                acc[1][0] = fmaf(hv.y, wv.x, acc[1][0]);
                acc[1][1] = fmaf(hv.y, wv.y, acc[1][1]);
                acc[2][0] = fmaf(hv.z, wv.x, acc[2][0]);
                acc[2][1] = fmaf(hv.z, wv.y, acc[2][1]);
                acc[3][0] = fmaf(hv.w, wv.x, acc[3][0]);
                acc[3][1] = fmaf(hv.w, wv.y, acc[3][1]);
            }
        }
        // bias + tanh + store this prefix level
        const float bb0 = b2s[(size_t)j * DDIM + d0 + dg * 2];
        const float bb1 = b2s[(size_t)j * DDIM + d0 + dg * 2 + 1];
#pragma unroll
        for (int i = 0; i < 4; i++) {
            acc[i][0] += bb0;
            acc[i][1] += bb1;
            int b = b0 + bg * 4 + i;
            float2 o = make_float2(tanhf(acc[i][0]), tanhf(acc[i][1]));
            *(float2*)&out[((size_t)j * BATCH + b) * DDIM + d0 + dg * 2] = o;
        }
    }
}

// ---------------- launch ---------------------------------------------------
extern "C" void kernel_launch(void* const* d_in, const int* in_sizes, int n_in,
                              void* d_out, int out_size)
{
    const float* x   = (const float*)d_in[0];   // (B,D)
    const float* We1 = (const float*)d_in[1];   // (H,D)
    const float* be1 = (const float*)d_in[2];   // (H,)
    const float* We2 = (const float*)d_in[3];   // (D,H)
    const float* be2 = (const float*)d_in[4];   // (D,)
    const float* W1s = (const float*)d_in[5];   // (D,H)
    const float* b1s = (const float*)d_in[6];   // (D,H)
    const float* W2s = (const float*)d_in[7];   // (D,D,H)
    const float* b2s = (const float*)d_in[8];   // (D,D)
    float* out = (float*)d_out;                 // (D,B,D)

    float *ench, *enc, *w2t;
    cudaGetSymbolAddress((void**)&ench, g_ench);
    cudaGetSymbolAddress((void**)&enc,  g_enc);
    cudaGetSymbolAddress((void**)&w2t,  g_w2t);

    // one-time transpose of W2s (captured into the graph; cheap, ~10us)
    transpose_w2<<<dim3(DDIM / 32, HDIM / 32, DDIM), dim3(32, 8)>>>(W2s, w2t);

    // encoder: enc_h = leaky(x @ We1^T + be1)
    gemm_nt_bias_act<<<dim3(BATCH / 64, HDIM / 64), 256>>>(
        x, We1, be1, ench, BATCH, HDIM, DDIM, /*act=*/0);
    // encoded = tanh(enc_h @ We2^T + be2)
    gemm_nt_bias_act<<<dim3(BATCH / 64, DDIM / 64), 256>>>(
        ench, We2, be2, enc, BATCH, DDIM, HDIM, /*act=*/1);

    // fused decoders + cumsum + tanh
    decoder_kernel<<<dim3(BATCH / BT, DDIM / DT), 256>>>(
        enc, W1s, b1s, w2t, b2s, out);
}

// round 2
// speedup vs baseline: 2.6220x; 2.6220x over previous
#include <cuda_runtime.h>
#include <cuda_bf16.h>
#include <math.h>

// Shapes (fixed per reference): B=2048, D=128, H=512
#define BATCH 2048
#define DDIM  128
#define HDIM  512

// ---------------- device scratch (static; no allocations) ----------------
__device__ float g_ench [BATCH * HDIM];                 // 4 MB
__device__ float g_enc  [BATCH * DDIM];                 // 1 MB
__device__ float g_w2t  [DDIM * HDIM * DDIM];           // 33.5 MB  (j,h,d)
__device__ float g_terms[DDIM * BATCH * DDIM];          // 134 MB   (j,b,d)

// ---------------- kernel 1: generic NT GEMM + bias + activation ----------
__global__ void gemm_nt_bias_act(const float* __restrict__ A,
                                 const float* __restrict__ Bw,
                                 const float* __restrict__ bias,
                                 float* __restrict__ C,
                                 int M, int N, int K, int act)
{
    __shared__ __align__(16) float As[32][68];
    __shared__ __align__(16) float Bs[32][68];

    const int t  = threadIdx.x;
    const int m0 = blockIdx.x * 64;
    const int n0 = blockIdx.y * 64;
    const int mg = t >> 4;
    const int ng = t & 15;

    float acc[4][4] = {};

    for (int k0 = 0; k0 < K; k0 += 32) {
        __syncthreads();
#pragma unroll
        for (int i = 0; i < 8; i++) {
            int idx = i * 256 + t;
            int m = idx >> 5, k = idx & 31;
            As[k][m] = A [(size_t)(m0 + m) * K + k0 + k];
            Bs[k][m] = Bw[(size_t)(n0 + m) * K + k0 + k];
        }
        __syncthreads();
#pragma unroll
        for (int k = 0; k < 32; k++) {
            float4 av = *(const float4*)&As[k][mg * 4];
            float4 bv = *(const float4*)&Bs[k][ng * 4];
            float a[4] = {av.x, av.y, av.z, av.w};
            float b[4] = {bv.x, bv.y, bv.z, bv.w};
#pragma unroll
            for (int i = 0; i < 4; i++)
#pragma unroll
                for (int jj = 0; jj < 4; jj++)
                    acc[i][jj] = fmaf(a[i], b[jj], acc[i][jj]);
        }
    }

#pragma unroll
    for (int i = 0; i < 4; i++) {
        int m = m0 + mg * 4 + i;
#pragma unroll
        for (int jj = 0; jj < 4; jj++) {
            int n = n0 + ng * 4 + jj;
            float c = acc[i][jj] + bias[n];
            c = (act == 0) ? fmaxf(c, 0.2f * c) : tanhf(c);
            C[(size_t)m * N + n] = c;
        }
    }
}

// ---------------- kernel 2: W2s (j,d,h) -> W2T (j,h,d) --------------------
__global__ void transpose_w2(const float* __restrict__ W2s, float* __restrict__ W2T)
{
    __shared__ float s[32][33];
    const int j  = blockIdx.z;
    const int d0 = blockIdx.x * 32;
    const int h0 = blockIdx.y * 32;
    const int tx = threadIdx.x, ty = threadIdx.y;

    const float* src = W2s + (size_t)j * DDIM * HDIM;
    float*       dst = W2T + (size_t)j * HDIM * DDIM;

#pragma unroll
    for (int i = 0; i < 32; i += 8)
        s[ty + i][tx] = src[(size_t)(d0 + ty + i) * HDIM + h0 + tx];
    __syncthreads();
#pragma unroll
    for (int i = 0; i < 32; i += 8)
        dst[(size_t)(h0 + ty + i) * DDIM + d0 + tx] = s[tx][ty + i];
}

// ---------------- kernel 3: per-j terms GEMM (no cumsum) -------------------
// terms[j][b][d] = sum_h leaky(z[j,b]*W1s[j,h]+b1s[j,h]) * W2T[j][h][d]
// One CTA: j = blockIdx.y, b-tile of 128 (blockIdx.x), full d=128.
// 256 threads, thread tile 8b x 8d (split d: {dg*4, 64+dg*4}).
#define HC 32
__global__ __launch_bounds__(256, 2)
void terms_kernel(const float* __restrict__ encoded,
                  const float* __restrict__ W1s,
                  const float* __restrict__ b1s,
                  const float* __restrict__ w2t,
                  float* __restrict__ terms)
{
    __shared__ __align__(16) float hid_s[HC][128];   // 16 KB
    __shared__ __align__(16) float w2_s [HC][128];   // 16 KB
    __shared__ float w1_s[HDIM];                     // 2 KB
    __shared__ float b1_s[HDIM];                     // 2 KB
    __shared__ float z_s [128];

    const int t  = threadIdx.x;            // 0..255
    const int j  = blockIdx.y;
    const int b0 = blockIdx.x * 128;
    const int bg = t >> 4;                 // 0..15 -> 8 consecutive b
    const int dg = t & 15;                 // 0..15 -> d cols {dg*4.., 64+dg*4..}

    w1_s[t]       = W1s[(size_t)j * HDIM + t];
    w1_s[t + 256] = W1s[(size_t)j * HDIM + t + 256];
    b1_s[t]       = b1s[(size_t)j * HDIM + t];
    b1_s[t + 256] = b1s[(size_t)j * HDIM + t + 256];
    if (t < 128) z_s[t] = encoded[(size_t)(b0 + t) * DDIM + j];

    float acc[8][8] = {};

    for (int hc = 0; hc < HDIM; hc += HC) {
        __syncthreads();   // prior chunk consumed (first iter: w1/b1/z ready)
        // fill hid chunk: 32h x 128b, conflict-free stores
#pragma unroll
        for (int i = 0; i < 16; i++) {
            int idx = i * 256 + t;
            int k = idx >> 7, b = idx & 127;
            float v = fmaf(z_s[b], w1_s[hc + k], b1_s[hc + k]);
            hid_s[k][b] = fmaxf(v, 0.2f * v);
        }
        // load W2T chunk as float4, fully coalesced
#pragma unroll
        for (int i = 0; i < 4; i++) {
            int idx = i * 256 + t;
            int k = idx >> 5, dq = idx & 31;
            *(float4*)&w2_s[k][dq * 4] =
                *(const float4*)&w2t[((size_t)j * HDIM + hc + k) * DDIM + dq * 4];
        }
        __syncthreads();
#pragma unroll 4
        for (int k = 0; k < HC; k++) {
            float4 hv0 = *(const float4*)&hid_s[k][bg * 8];
            float4 hv1 = *(const float4*)&hid_s[k][bg * 8 + 4];
            float4 wv0 = *(const float4*)&w2_s[k][dg * 4];
            float4 wv1 = *(const float4*)&w2_s[k][64 + dg * 4];
            float hb[8] = {hv0.x, hv0.y, hv0.z, hv0.w, hv1.x, hv1.y, hv1.z, hv1.w};
            float wd[8] = {wv0.x, wv0.y, wv0.z, wv0.w, wv1.x, wv1.y, wv1.z, wv1.w};
#pragma unroll
            for (int i = 0; i < 8; i++)
#pragma unroll
                for (int c = 0; c < 8; c++)
                    acc[i][c] = fmaf(hb[i], wd[c], acc[i][c]);
        }
    }

    // epilogue: raw terms (bias added in phase 2)
#pragma unroll
    for (int i = 0; i < 8; i++) {
        int b = b0 + bg * 8 + i;
        float* row = terms + ((size_t)j * BATCH + b) * DDIM;
        float4 lo = make_float4(acc[i][0], acc[i][1], acc[i][2], acc[i][3]);
        float4 hi = make_float4(acc[i][4], acc[i][5], acc[i][6], acc[i][7]);
        *(float4*)&row[dg * 4]      = lo;
        *(float4*)&row[64 + dg * 4] = hi;
    }
}

// ---------------- kernel 4: cumsum over j + bias + tanh --------------------
// thread handles one (b, 4d) column; streams 128 j levels.
__global__ __launch_bounds__(256)
void cumsum_tanh(const float* __restrict__ terms,
                 const float* __restrict__ b2s,
                 float* __restrict__ out)
{
    const int g  = blockIdx.x * 256 + threadIdx.x;   // 0..65535
    const int dq = g & 31;                            // float4 index within d
    const size_t col = (size_t)g;                     // b*32+dq
    const size_t jstride = (size_t)BATCH * DDIM / 4;  // float4s per j level

    const float4* tp = (const float4*)terms + col;
    float4*       op = (float4*)out + col;
    const float4* bp = (const float4*)b2s + dq;

    float4 acc = make_float4(0.f, 0.f, 0.f, 0.f);
#pragma unroll 2
    for (int j = 0; j < DDIM; j++) {
        float4 tv = tp[(size_t)j * jstride];
        float4 bv = bp[(size_t)j * (DDIM / 4)];
        acc.x += tv.x + bv.x;
        acc.y += tv.y + bv.y;
        acc.z += tv.z + bv.z;
        acc.w += tv.w + bv.w;
        float4 o = make_float4(tanhf(acc.x), tanhf(acc.y), tanhf(acc.z), tanhf(acc.w));
        op[(size_t)j * jstride] = o;
    }
}

// ---------------- launch ---------------------------------------------------
extern "C" void kernel_launch(void* const* d_in, const int* in_sizes, int n_in,
                              void* d_out, int out_size)
{
    const float* x   = (const float*)d_in[0];
    const float* We1 = (const float*)d_in[1];
    const float* be1 = (const float*)d_in[2];
    const float* We2 = (const float*)d_in[3];
    const float* be2 = (const float*)d_in[4];
    const float* W1s = (const float*)d_in[5];
    const float* b1s = (const float*)d_in[6];
    const float* W2s = (const float*)d_in[7];
    const float* b2s = (const float*)d_in[8];
    float* out = (float*)d_out;

    float *ench, *enc, *w2t, *terms;
    cudaGetSymbolAddress((void**)&ench,  g_ench);
    cudaGetSymbolAddress((void**)&enc,   g_enc);
    cudaGetSymbolAddress((void**)&w2t,   g_w2t);
    cudaGetSymbolAddress((void**)&terms, g_terms);

    transpose_w2<<<dim3(DDIM / 32, HDIM / 32, DDIM), dim3(32, 8)>>>(W2s, w2t);

    gemm_nt_bias_act<<<dim3(BATCH / 64, HDIM / 64), 256>>>(
        x, We1, be1, ench, BATCH, HDIM, DDIM, 0);
    gemm_nt_bias_act<<<dim3(BATCH / 64, DDIM / 64), 256>>>(
        ench, We2, be2, enc, BATCH, DDIM, HDIM, 1);

    // phase 1: 2048 CTAs, FFMA-bound
    terms_kernel<<<dim3(BATCH / 128, DDIM), 256>>>(enc, W1s, b1s, w2t, terms);

    // phase 2: streaming cumsum + bias + tanh
    cumsum_tanh<<<(BATCH * DDIM / 4) / 256, 256>>>(terms, b2s, out);
}

// round 4
// speedup vs baseline: 5.2813x; 2.0142x over previous
#include <cuda_runtime.h>
#include <cuda_bf16.h>
#include <math.h>
#include <stdint.h>

// Shapes (fixed): B=2048, D=128, H=512
#define BATCH 2048
#define DDIM  128
#define HDIM  512

// ---------------- device scratch (static; no allocations) ----------------
__device__ float g_ench [BATCH * HDIM];                  // 4 MB
__device__ float g_enc  [BATCH * DDIM];                  // 1 MB
__device__ float g_terms[DDIM * BATCH * DDIM];           // 134 MB (j,b,d)
__device__ __nv_bfloat16 g_w2hi[DDIM * DDIM * HDIM];     // 16.8 MB (j,d,h)
__device__ __nv_bfloat16 g_w2lo[DDIM * DDIM * HDIM];     // 16.8 MB

// ======================= helpers ==========================================
__device__ __forceinline__ uint32_t smem_u32(const void* p) {
    uint32_t a;
    asm("{ .reg .u64 t; cvta.to.shared.u64 t, %1; cvt.u32.u64 %0, t; }"
        : "=r"(a) : "l"(p));
    return a;
}
__device__ __forceinline__ uint32_t pack2(float a, float b) {
    __nv_bfloat162 t = __floats2bfloat162_rn(a, b);
    return *reinterpret_cast<uint32_t*>(&t);
}
// SW128-style swizzle: 128B rows, XOR bits[6:4] with row&7
__device__ __forceinline__ uint32_t sw_off(int row, int colb) {
    return (uint32_t)(row * 128 + (colb ^ ((row & 7) << 4)));
}
#define LDSM_X4(r0, r1, r2, r3, addr)                                          \
    asm volatile("ldmatrix.sync.aligned.m8n8.x4.shared.b16 {%0,%1,%2,%3}, [%4];" \
                 : "=r"(r0), "=r"(r1), "=r"(r2), "=r"(r3) : "r"(addr))
#define MMA_BF16(d, a, b)                                                      \
    asm volatile("mma.sync.aligned.m16n8k16.row.col.f32.bf16.bf16.f32 "        \
                 "{%0,%1,%2,%3}, {%4,%5,%6,%7}, {%8,%9}, {%0,%1,%2,%3};"       \
                 : "+f"((d)[0]), "+f"((d)[1]), "+f"((d)[2]), "+f"((d)[3])      \
                 : "r"((a)[0]), "r"((a)[1]), "r"((a)[2]), "r"((a)[3]),         \
                   "r"((b)[0]), "r"((b)[1]))
#define CP_ASYNC16(saddr, gptr)                                                \
    asm volatile("cp.async.cg.shared.global [%0], [%1], 16;"                   \
                 :: "r"(saddr), "l"(gptr) : "memory")
#define CP_COMMIT()  asm volatile("cp.async.commit_group;" ::: "memory")
#define CP_WAIT0()   asm volatile("cp.async.wait_group 0;" ::: "memory")

// ---------------- kernel 1: generic NT GEMM + bias + activation ----------
__global__ void gemm_nt_bias_act(const float* __restrict__ A,
                                 const float* __restrict__ Bw,
                                 const float* __restrict__ bias,
                                 float* __restrict__ C,
                                 int M, int N, int K, int act)
{
    __shared__ __align__(16) float As[32][68];
    __shared__ __align__(16) float Bs[32][68];

    const int t  = threadIdx.x;
    const int m0 = blockIdx.x * 64;
    const int n0 = blockIdx.y * 64;
    const int mg = t >> 4;
    const int ng = t & 15;

    float acc[4][4] = {};

    for (int k0 = 0; k0 < K; k0 += 32) {
        __syncthreads();
#pragma unroll
        for (int i = 0; i < 8; i++) {
            int idx = i * 256 + t;
            int m = idx >> 5, k = idx & 31;
            As[k][m] = A [(size_t)(m0 + m) * K + k0 + k];
            Bs[k][m] = Bw[(size_t)(n0 + m) * K + k0 + k];
        }
        __syncthreads();
#pragma unroll
        for (int k = 0; k < 32; k++) {
            float4 av = *(const float4*)&As[k][mg * 4];
            float4 bv = *(const float4*)&Bs[k][ng * 4];
            float a[4] = {av.x, av.y, av.z, av.w};
            float b[4] = {bv.x, bv.y, bv.z, bv.w};
#pragma unroll
            for (int i = 0; i < 4; i++)
#pragma unroll
                for (int jj = 0; jj < 4; jj++)
                    acc[i][jj] = fmaf(a[i], b[jj], acc[i][jj]);
        }
    }

#pragma unroll
    for (int i = 0; i < 4; i++) {
        int m = m0 + mg * 4 + i;
#pragma unroll
        for (int jj = 0; jj < 4; jj++) {
            int n = n0 + ng * 4 + jj;
            float c = acc[i][jj] + bias[n];
            c = (act == 0) ? fmaxf(c, 0.2f * c) : tanhf(c);
            C[(size_t)m * N + n] = c;
        }
    }
}

// ---------------- kernel 2: split W2s fp32 -> bf16 hi/lo -------------------
__global__ void w2_split_kernel(const float4* __restrict__ w2,
                                uint2* __restrict__ hi, uint2* __restrict__ lo)
{
    int i = blockIdx.x * blockDim.x + threadIdx.x;
    float4 v = w2[i];
    __nv_bfloat16 h0 = __float2bfloat16(v.x), h1 = __float2bfloat16(v.y);
    __nv_bfloat16 h2 = __float2bfloat16(v.z), h3 = __float2bfloat16(v.w);
    float r0 = v.x - __bfloat162float(h0), r1 = v.y - __bfloat162float(h1);
    float r2 = v.z - __bfloat162float(h2), r3 = v.w - __bfloat162float(h3);
    uint2 H, L;
    H.x = pack2(__bfloat162float(h0), __bfloat162float(h1));
    H.y = pack2(__bfloat162float(h2), __bfloat162float(h3));
    L.x = pack2(r0, r1);
    L.y = pack2(r2, r3);
    hi[i] = H;
    lo[i] = L;
}

// ---------------- kernel 3: terms via mma.sync (bf16-split) ----------------
// terms[j][b][d] = sum_h leaky(z*w1+b1) * W2[j][d][h]
// CTA: (j, b-tile 128) x d 128, K=512 in 8 chunks of 64. 8 warps, 64x32 tiles.
#define KC 64
#define SM_Z     0
#define SM_W1    512
#define SM_B1    2560
#define SM_TILE0 4608
#define MAT_SZ   16384                    // 128 x 64 bf16
#define BUF_SZ   (4 * MAT_SZ)             // Ahi, Alo, Bhi, Blo
#define S_AHI(b) (SM_TILE0 + (b) * BUF_SZ)
#define S_ALO(b) (SM_TILE0 + (b) * BUF_SZ + MAT_SZ)
#define S_BHI(b) (SM_TILE0 + (b) * BUF_SZ + 2 * MAT_SZ)
#define S_BLO(b) (SM_TILE0 + (b) * BUF_SZ + 3 * MAT_SZ)
#define SMEM_TOTAL (SM_TILE0 + 2 * BUF_SZ)   // 135680 B

__global__ __launch_bounds__(256, 1)
void terms_mma_kernel(const float* __restrict__ encoded,
                      const float* __restrict__ W1s,
                      const float* __restrict__ b1s,
                      const __nv_bfloat16* __restrict__ w2hi,
                      const __nv_bfloat16* __restrict__ w2lo,
                      float* __restrict__ terms)
{
    extern __shared__ __align__(128) char smem[];
    const uint32_t sbase = smem_u32(smem);
    const int t   = threadIdx.x;
    const int l   = t & 31;
    const int wid = t >> 5;
    const int j   = blockIdx.y;
    const int b0  = blockIdx.x * 128;

    float* z_s  = (float*)(smem + SM_Z);
    float* w1_s = (float*)(smem + SM_W1);
    float* b1_s = (float*)(smem + SM_B1);

    w1_s[t]       = W1s[(size_t)j * HDIM + t];
    w1_s[t + 256] = W1s[(size_t)j * HDIM + t + 256];
    b1_s[t]       = b1s[(size_t)j * HDIM + t];
    b1_s[t + 256] = b1s[(size_t)j * HDIM + t + 256];
    if (t < 128) z_s[t] = encoded[(size_t)(b0 + t) * DDIM + j];
    __syncthreads();

    // ---- per-thread constants ----
    const int m0 = (wid & 1) * 64;              // warp m origin (b)
    const int n0 = (wid >> 1) * 32;             // warp n origin (d)
    // A ldmatrix lane mapping
    const int ar  = ((l >> 3) & 1) * 8 + (l & 7);
    const int ac2 = (l >> 4) * 16;              // k-offset*2 bytes
    const uint32_t swA = (uint32_t)((ar & 7) << 4);
    // B ldmatrix lane mapping
    const int br  = (l >> 4) * 8 + (l & 7);
    const int bc2 = ((l >> 3) & 1) * 16;
    const uint32_t swB = (uint32_t)((br & 7) << 4);
    // producer mappings
    const int pb    = t & 127;                  // hid row (b)
    const int phb   = (t >> 7) * 32;            // hid h base within chunk
    const float z   = (t < 256) ? z_s[pb] : 0.f;
    const int bseg  = t & 7;                    // B 16B segment
    const int bd0   = t >> 3;                   // B d base (0..31)

    float acc[4][4][4] = {};

    // ---- producers ----
    auto loadB = [&](int c, int buf) {
        const int hc = c * KC;
#pragma unroll
        for (int p = 0; p < 4; ++p) {
            const int d = p * 32 + bd0;
            const size_t goff = ((size_t)j * DDIM + d) * HDIM + hc + bseg * 8;
            const uint32_t so = sw_off(d, bseg * 16);
            CP_ASYNC16(sbase + S_BHI(buf) + so, w2hi + goff);
            CP_ASYNC16(sbase + S_BLO(buf) + so, w2lo + goff);
        }
    };
    auto storeA = [&](int c, int buf) {
        const int hc = c * KC;
#pragma unroll
        for (int i = 0; i < 4; ++i) {
            const int h = phb + i * 8;
            float v[8], r[8];
#pragma unroll
            for (int q = 0; q < 8; ++q) {
                float u = fmaf(z, w1_s[hc + h + q], b1_s[hc + h + q]);
                u = fmaxf(u, 0.2f * u);
                __nv_bfloat16 hb = __float2bfloat16(u);
                float hf = __bfloat162float(hb);
                v[q] = hf;
                r[q] = u - hf;
            }
            uint4 H, L;
            H.x = pack2(v[0], v[1]); H.y = pack2(v[2], v[3]);
            H.z = pack2(v[4], v[5]); H.w = pack2(v[6], v[7]);
            L.x = pack2(r[0], r[1]); L.y = pack2(r[2], r[3]);
            L.z = pack2(r[4], r[5]); L.w = pack2(r[6], r[7]);
            const uint32_t so = sw_off(pb, h * 2);
            *(uint4*)(smem + S_AHI(buf) + so) = H;
            *(uint4*)(smem + S_ALO(buf) + so) = L;
        }
    };

    // ---- consumer: one KC chunk of MMAs ----
    auto hmma = [&](int buf) {
        const uint32_t aHi = sbase + S_AHI(buf), aLo = sbase + S_ALO(buf);
        const uint32_t bHi = sbase + S_BHI(buf), bLo = sbase + S_BLO(buf);
#pragma unroll
        for (int ks = 0; ks < KC / 16; ++ks) {
            const int kb = ks * 32;   // byte col base
            uint32_t bh[4][2], bl[4][2];
#pragma unroll
            for (int np = 0; np < 2; ++np) {
                const uint32_t ro = (uint32_t)((n0 + np * 16 + br) * 128);
                const uint32_t co = (uint32_t)(kb + bc2) ^ swB;
                LDSM_X4(bh[np*2][0], bh[np*2][1], bh[np*2+1][0], bh[np*2+1][1],
                        bHi + ro + co);
                LDSM_X4(bl[np*2][0], bl[np*2][1], bl[np*2+1][0], bl[np*2+1][1],
                        bLo + ro + co);
            }
#pragma unroll
            for (int mt = 0; mt < 4; ++mt) {
                const uint32_t ro = (uint32_t)((m0 + mt * 16 + ar) * 128);
                const uint32_t co = (uint32_t)(kb + ac2) ^ swA;
                uint32_t ah[4], al[4];
                LDSM_X4(ah[0], ah[1], ah[2], ah[3], aHi + ro + co);
                LDSM_X4(al[0], al[1], al[2], al[3], aLo + ro + co);
#pragma unroll
                for (int nt = 0; nt < 4; ++nt) {
                    MMA_BF16(acc[mt][nt], ah, bh[nt]);
                    MMA_BF16(acc[mt][nt], ah, bl[nt]);
                    MMA_BF16(acc[mt][nt], al, bh[nt]);
                }
            }
        }
    };

    // ---- pipeline ----
    loadB(0, 0);
    CP_COMMIT();
    storeA(0, 0);
    CP_WAIT0();
    __syncthreads();

    for (int c = 0; c < HDIM / KC; ++c) {
        const int buf = c & 1;
        if (c < HDIM / KC - 1) { loadB(c + 1, buf ^ 1); CP_COMMIT(); }
        hmma(buf);
        if (c < HDIM / KC - 1) {
            storeA(c + 1, buf ^ 1);
            CP_WAIT0();
            __syncthreads();
        }
    }

    // ---- epilogue: direct fp32 stores ----
    const int t4 = l >> 2, tn = (l & 3) * 2;
#pragma unroll
    for (int mt = 0; mt < 4; ++mt) {
        const int row0 = b0 + m0 + mt * 16 + t4;
        float* p0 = terms + ((size_t)j * BATCH + row0) * DDIM;
        float* p1 = terms + ((size_t)j * BATCH + row0 + 8) * DDIM;
#pragma unroll
        for (int nt = 0; nt < 4; ++nt) {
            const int col = n0 + nt * 8 + tn;
            *(float2*)&p0[col] = make_float2(acc[mt][nt][0], acc[mt][nt][1]);
            *(float2*)&p1[col] = make_float2(acc[mt][nt][2], acc[mt][nt][3]);
        }
    }
}

// ---------------- kernel 4: cumsum over j + bias + tanh --------------------
__global__ __launch_bounds__(256)
void cumsum_tanh(const float* __restrict__ terms,
                 const float* __restrict__ b2s,
                 float* __restrict__ out)
{
    const int g  = blockIdx.x * 256 + threadIdx.x;
    const int dq = g & 31;
    const size_t jstride = (size_t)BATCH * DDIM / 4;

    const float4* tp = (const float4*)terms + g;
    float4*       op = (float4*)out + g;
    const float4* bp = (const float4*)b2s + dq;

    float4 acc = make_float4(0.f, 0.f, 0.f, 0.f);
#pragma unroll 4
    for (int j = 0; j < DDIM; j++) {
        float4 tv = tp[(size_t)j * jstride];
        float4 bv = bp[(size_t)j * (DDIM / 4)];
        acc.x += tv.x + bv.x;
        acc.y += tv.y + bv.y;
        acc.z += tv.z + bv.z;
        acc.w += tv.w + bv.w;
        float4 o = make_float4(tanhf(acc.x), tanhf(acc.y),
                               tanhf(acc.z), tanhf(acc.w));
        op[(size_t)j * jstride] = o;
    }
}

// ---------------- launch ---------------------------------------------------
extern "C" void kernel_launch(void* const* d_in, const int* in_sizes, int n_in,
                              void* d_out, int out_size)
{
    const float* x   = (const float*)d_in[0];
    const float* We1 = (const float*)d_in[1];
    const float* be1 = (const float*)d_in[2];
    const float* We2 = (const float*)d_in[3];
    const float* be2 = (const float*)d_in[4];
    const float* W1s = (const float*)d_in[5];
    const float* b1s = (const float*)d_in[6];
    const float* W2s = (const float*)d_in[7];
    const float* b2s = (const float*)d_in[8];
    float* out = (float*)d_out;

    float *ench, *enc, *terms;
    __nv_bfloat16 *w2hi, *w2lo;
    cudaGetSymbolAddress((void**)&ench,  g_ench);
    cudaGetSymbolAddress((void**)&enc,   g_enc);
    cudaGetSymbolAddress((void**)&terms, g_terms);
    cudaGetSymbolAddress((void**)&w2hi,  g_w2hi);
    cudaGetSymbolAddress((void**)&w2lo,  g_w2lo);

    cudaFuncSetAttribute(terms_mma_kernel,
                         cudaFuncAttributeMaxDynamicSharedMemorySize, SMEM_TOTAL);

    w2_split_kernel<<<(DDIM * DDIM * HDIM / 4) / 256, 256>>>(
        (const float4*)W2s, (uint2*)w2hi, (uint2*)w2lo);

    gemm_nt_bias_act<<<dim3(BATCH / 64, HDIM / 64), 256>>>(
        x, We1, be1, ench, BATCH, HDIM, DDIM, 0);
    gemm_nt_bias_act<<<dim3(BATCH / 64, DDIM / 64), 256>>>(
        ench, We2, be2, enc, BATCH, DDIM, HDIM, 1);

    terms_mma_kernel<<<dim3(BATCH / 128, DDIM), 256, SMEM_TOTAL>>>(
        enc, W1s, b1s, w2hi, w2lo, terms);

    cumsum_tanh<<<(BATCH * DDIM / 4) / 256, 256>>>(terms, b2s, out);
}

// round 5
// speedup vs baseline: 6.0007x; 1.1362x over previous
#include <cuda_runtime.h>
#include <cuda_bf16.h>
#include <math.h>
#include <stdint.h>

// Shapes (fixed): B=2048, D=128, H=512
#define BATCH 2048
#define DDIM  128
#define HDIM  512

// ---------------- device scratch (static; no allocations) ----------------
__device__ float g_ench [BATCH * HDIM];                  // 4 MB
__device__ float g_enc  [BATCH * DDIM];                  // 1 MB
__device__ float g_terms[DDIM * BATCH * DDIM];           // 134 MB (j,b,d)
__device__ __nv_bfloat16 g_w2hi[DDIM * DDIM * HDIM];     // 16.8 MB (j,d,h)
__device__ __nv_bfloat16 g_w2lo[DDIM * DDIM * HDIM];     // 16.8 MB

// ======================= helpers ==========================================
__device__ __forceinline__ uint32_t smem_u32(const void* p) {
    uint32_t a;
    asm("{ .reg .u64 t; cvta.to.shared.u64 t, %1; cvt.u32.u64 %0, t; }"
        : "=r"(a) : "l"(p));
    return a;
}
__device__ __forceinline__ uint32_t pack2(float a, float b) {
    __nv_bfloat162 t = __floats2bfloat162_rn(a, b);
    return *reinterpret_cast<uint32_t*>(&t);
}
// SW128-style swizzle: 128B rows, XOR bits[6:4] with row&7
__device__ __forceinline__ uint32_t sw_off(int row, int colb) {
    return (uint32_t)(row * 128 + (colb ^ ((row & 7) << 4)));
}
#define LDSM_X4(r0, r1, r2, r3, addr)                                          \
    asm volatile("ldmatrix.sync.aligned.m8n8.x4.shared.b16 {%0,%1,%2,%3}, [%4];" \
                 : "=r"(r0), "=r"(r1), "=r"(r2), "=r"(r3) : "r"(addr))
#define MMA_BF16(d, a, b)                                                      \
    asm volatile("mma.sync.aligned.m16n8k16.row.col.f32.bf16.bf16.f32 "        \
                 "{%0,%1,%2,%3}, {%4,%5,%6,%7}, {%8,%9}, {%0,%1,%2,%3};"       \
                 : "+f"((d)[0]), "+f"((d)[1]), "+f"((d)[2]), "+f"((d)[3])      \
                 : "r"((a)[0]), "r"((a)[1]), "r"((a)[2]), "r"((a)[3]),         \
                   "r"((b)[0]), "r"((b)[1]))
#define CP_ASYNC16(saddr, gptr)                                                \
    asm volatile("cp.async.cg.shared.global [%0], [%1], 16;"                   \
                 :: "r"(saddr), "l"(gptr) : "memory")
#define CP_COMMIT()  asm volatile("cp.async.commit_group;" ::: "memory")
#define CP_WAIT0()   asm volatile("cp.async.wait_group 0;" ::: "memory")

// ---------------- kernel 1: generic NT GEMM + bias + activation ----------
__global__ void gemm_nt_bias_act(const float* __restrict__ A,
                                 const float* __restrict__ Bw,
                                 const float* __restrict__ bias,
                                 float* __restrict__ C,
                                 int M, int N, int K, int act)
{
    __shared__ __align__(16) float As[32][68];
    __shared__ __align__(16) float Bs[32][68];

    const int t  = threadIdx.x;
    const int m0 = blockIdx.x * 64;
    const int n0 = blockIdx.y * 64;
    const int mg = t >> 4;
    const int ng = t & 15;

    float acc[4][4] = {};

    for (int k0 = 0; k0 < K; k0 += 32) {
        __syncthreads();
#pragma unroll
        for (int i = 0; i < 8; i++) {
            int idx = i * 256 + t;
            int m = idx >> 5, k = idx & 31;
            As[k][m] = A [(size_t)(m0 + m) * K + k0 + k];
            Bs[k][m] = Bw[(size_t)(n0 + m) * K + k0 + k];
        }
        __syncthreads();
#pragma unroll
        for (int k = 0; k < 32; k++) {
            float4 av = *(const float4*)&As[k][mg * 4];
            float4 bv = *(const float4*)&Bs[k][ng * 4];
            float a[4] = {av.x, av.y, av.z, av.w};
            float b[4] = {bv.x, bv.y, bv.z, bv.w};
#pragma unroll
            for (int i = 0; i < 4; i++)
#pragma unroll
                for (int jj = 0; jj < 4; jj++)
                    acc[i][jj] = fmaf(a[i], b[jj], acc[i][jj]);
        }
    }

#pragma unroll
    for (int i = 0; i < 4; i++) {
        int m = m0 + mg * 4 + i;
#pragma unroll
        for (int jj = 0; jj < 4; jj++) {
            int n = n0 + ng * 4 + jj;
            float c = acc[i][jj] + bias[n];
            c = (act == 0) ? fmaxf(c, 0.2f * c) : tanhf(c);
            C[(size_t)m * N + n] = c;
        }
    }
}

// ---------------- kernel 2: split W2s fp32 -> bf16 hi/lo -------------------
__global__ void w2_split_kernel(const float4* __restrict__ w2,
                                uint2* __restrict__ hi, uint2* __restrict__ lo)
{
    int i = blockIdx.x * blockDim.x + threadIdx.x;
    float4 v = w2[i];
    __nv_bfloat16 h0 = __float2bfloat16(v.x), h1 = __float2bfloat16(v.y);
    __nv_bfloat16 h2 = __float2bfloat16(v.z), h3 = __float2bfloat16(v.w);
    float r0 = v.x - __bfloat162float(h0), r1 = v.y - __bfloat162float(h1);
    float r2 = v.z - __bfloat162float(h2), r3 = v.w - __bfloat162float(h3);
    uint2 H, L;
    H.x = pack2(__bfloat162float(h0), __bfloat162float(h1));
    H.y = pack2(__bfloat162float(h2), __bfloat162float(h3));
    L.x = pack2(r0, r1);
    L.y = pack2(r2, r3);
    hi[i] = H;
    lo[i] = L;
}

// ---------------- kernel 3: terms via mma.sync (bf16-split) ----------------
// terms[j][b][d] = sum_h leaky(z*w1+b1) * W2[j][d][h]
// CTA: (j, b-tile 128) x d 128, K=512 in 8 chunks of 64. 8 warps, 64x32 tiles.
// SMEM slimmed: single A buffer + double B buffer -> 2 CTAs/SM.
#define KC 64
#define SM_Z     0
#define SM_W1    512
#define SM_B1    2560
#define SM_TILE0 4608
#define MAT_SZ   16384                    // 128 x 64 bf16
#define S_AHI    (SM_TILE0)
#define S_ALO    (SM_TILE0 + MAT_SZ)
#define S_B0     (SM_TILE0 + 2 * MAT_SZ)
#define S_BHI(b) (S_B0 + (b) * 2 * MAT_SZ)
#define S_BLO(b) (S_B0 + (b) * 2 * MAT_SZ + MAT_SZ)
#define SMEM_TOTAL (S_B0 + 4 * MAT_SZ)   // 102912 B

__global__ __launch_bounds__(256, 2)
void terms_mma_kernel(const float* __restrict__ encoded,
                      const float* __restrict__ W1s,
                      const float* __restrict__ b1s,
                      const __nv_bfloat16* __restrict__ w2hi,
                      const __nv_bfloat16* __restrict__ w2lo,
                      float* __restrict__ terms)
{
    extern __shared__ __align__(128) char smem[];
    const uint32_t sbase = smem_u32(smem);
    const int t   = threadIdx.x;
    const int l   = t & 31;
    const int wid = t >> 5;
    const int j   = blockIdx.y;
    const int b0  = blockIdx.x * 128;

    float* z_s  = (float*)(smem + SM_Z);
    float* w1_s = (float*)(smem + SM_W1);
    float* b1_s = (float*)(smem + SM_B1);

    w1_s[t]       = W1s[(size_t)j * HDIM + t];
    w1_s[t + 256] = W1s[(size_t)j * HDIM + t + 256];
    b1_s[t]       = b1s[(size_t)j * HDIM + t];
    b1_s[t + 256] = b1s[(size_t)j * HDIM + t + 256];
    if (t < 128) z_s[t] = encoded[(size_t)(b0 + t) * DDIM + j];
    __syncthreads();

    // ---- per-thread constants ----
    const int m0 = (wid & 1) * 64;              // warp m origin (b)
    const int n0 = (wid >> 1) * 32;             // warp n origin (d)
    const int ar  = ((l >> 3) & 1) * 8 + (l & 7);
    const int ac2 = (l >> 4) * 16;
    const uint32_t swA = (uint32_t)((ar & 7) << 4);
    const int br  = (l >> 4) * 8 + (l & 7);
    const int bc2 = ((l >> 3) & 1) * 16;
    const uint32_t swB = (uint32_t)((br & 7) << 4);
    const int pb    = t & 127;
    const int phb   = (t >> 7) * 32;
    const float z   = z_s[pb];
    const int bseg  = t & 7;
    const int bd0   = t >> 3;

    float acc[4][4][4] = {};

    auto loadB = [&](int c, int buf) {
        const int hc = c * KC;
#pragma unroll
        for (int p = 0; p < 4; ++p) {
            const int d = p * 32 + bd0;
            const size_t goff = ((size_t)j * DDIM + d) * HDIM + hc + bseg * 8;
            const uint32_t so = sw_off(d, bseg * 16);
            CP_ASYNC16(sbase + S_BHI(buf) + so, w2hi + goff);
            CP_ASYNC16(sbase + S_BLO(buf) + so, w2lo + goff);
        }
    };
    auto storeA = [&](int c) {
        const int hc = c * KC;
#pragma unroll
        for (int i = 0; i < 4; ++i) {
            const int h = phb + i * 8;
            float v[8], r[8];
#pragma unroll
            for (int q = 0; q < 8; ++q) {
                float u = fmaf(z, w1_s[hc + h + q], b1_s[hc + h + q]);
                u = fmaxf(u, 0.2f * u);
                __nv_bfloat16 hb = __float2bfloat16(u);
                float hf = __bfloat162float(hb);
                v[q] = hf;
                r[q] = u - hf;
            }
            uint4 H, L;
            H.x = pack2(v[0], v[1]); H.y = pack2(v[2], v[3]);
            H.z = pack2(v[4], v[5]); H.w = pack2(v[6], v[7]);
            L.x = pack2(r[0], r[1]); L.y = pack2(r[2], r[3]);
            L.z = pack2(r[4], r[5]); L.w = pack2(r[6], r[7]);
            const uint32_t so = sw_off(pb, h * 2);
            *(uint4*)(smem + S_AHI + so) = H;
            *(uint4*)(smem + S_ALO + so) = L;
        }
    };

    auto hmma = [&](int buf) {
        const uint32_t aHi = sbase + S_AHI, aLo = sbase + S_ALO;
        const uint32_t bHi = sbase + S_BHI(buf), bLo = sbase + S_BLO(buf);
#pragma unroll
        for (int ks = 0; ks < KC / 16; ++ks) {
            const int kb = ks * 32;
            uint32_t bh[4][2], bl[4][2];
#pragma unroll
            for (int np = 0; np < 2; ++np) {
                const uint32_t ro = (uint32_t)((n0 + np * 16 + br) * 128);
                const uint32_t co = (uint32_t)(kb + bc2) ^ swB;
                LDSM_X4(bh[np*2][0], bh[np*2][1], bh[np*2+1][0], bh[np*2+1][1],
                        bHi + ro + co);
                LDSM_X4(bl[np*2][0], bl[np*2][1], bl[np*2+1][0], bl[np*2+1][1],
                        bLo + ro + co);
            }
#pragma unroll
            for (int mt = 0; mt < 4; ++mt) {
                const uint32_t ro = (uint32_t)((m0 + mt * 16 + ar) * 128);
                const uint32_t co = (uint32_t)(kb + ac2) ^ swA;
                uint32_t ah[4], al[4];
                LDSM_X4(ah[0], ah[1], ah[2], ah[3], aHi + ro + co);
                LDSM_X4(al[0], al[1], al[2], al[3], aLo + ro + co);
#pragma unroll
                for (int nt = 0; nt < 4; ++nt) {
                    MMA_BF16(acc[mt][nt], ah, bh[nt]);
                    MMA_BF16(acc[mt][nt], ah, bl[nt]);
                    MMA_BF16(acc[mt][nt], al, bh[nt]);
                }
            }
        }
    };

    // ---- pipeline: single A buffer, double B buffer ----
    loadB(0, 0);
    CP_COMMIT();
    storeA(0);
    CP_WAIT0();
    __syncthreads();

    for (int c = 0; c < HDIM / KC; ++c) {
        const int buf = c & 1;
        if (c < HDIM / KC - 1) { loadB(c + 1, buf ^ 1); CP_COMMIT(); }
        hmma(buf);
        if (c < HDIM / KC - 1) {
            __syncthreads();        // all warps finished reading A chunk c
            storeA(c + 1);          // overwrite single A buffer
            CP_WAIT0();
            __syncthreads();        // A(c+1) + B(c+1) visible
        }
    }

    // ---- epilogue: direct fp32 stores ----
    const int t4 = l >> 2, tn = (l & 3) * 2;
#pragma unroll
    for (int mt = 0; mt < 4; ++mt) {
        const int row0 = b0 + m0 + mt * 16 + t4;
        float* p0 = terms + ((size_t)j * BATCH + row0) * DDIM;
        float* p1 = terms + ((size_t)j * BATCH + row0 + 8) * DDIM;
#pragma unroll
        for (int nt = 0; nt < 4; ++nt) {
            const int col = n0 + nt * 8 + tn;
            *(float2*)&p0[col] = make_float2(acc[mt][nt][0], acc[mt][nt][1]);
            *(float2*)&p1[col] = make_float2(acc[mt][nt][2], acc[mt][nt][3]);
        }
    }
}

// ---------------- kernel 4: cumsum over j + bias + tanh --------------------
__global__ __launch_bounds__(256)
void cumsum_tanh(const float* __restrict__ terms,
                 const float* __restrict__ b2s,
                 float* __restrict__ out)
{
    const int g  = blockIdx.x * 256 + threadIdx.x;
    const int dq = g & 31;
    const size_t jstride = (size_t)BATCH * DDIM / 4;

    const float4* tp = (const float4*)terms + g;
    float4*       op = (float4*)out + g;
    const float4* bp = (const float4*)b2s + dq;

    float4 acc = make_float4(0.f, 0.f, 0.f, 0.f);
#pragma unroll 4
    for (int j = 0; j < DDIM; j++) {
        float4 tv = tp[(size_t)j * jstride];
        float4 bv = bp[(size_t)j * (DDIM / 4)];
        acc.x += tv.x + bv.x;
        acc.y += tv.y + bv.y;
        acc.z += tv.z + bv.z;
        acc.w += tv.w + bv.w;
        float4 o = make_float4(tanhf(acc.x), tanhf(acc.y),
                               tanhf(acc.z), tanhf(acc.w));
        op[(size_t)j * jstride] = o;
    }
}

// ---------------- launch ---------------------------------------------------
extern "C" void kernel_launch(void* const* d_in, const int* in_sizes, int n_in,
                              void* d_out, int out_size)
{
    const float* x   = (const float*)d_in[0];
    const float* We1 = (const float*)d_in[1];
    const float* be1 = (const float*)d_in[2];
    const float* We2 = (const float*)d_in[3];
    const float* be2 = (const float*)d_in[4];
    const float* W1s = (const float*)d_in[5];
    const float* b1s = (const float*)d_in[6];
    const float* W2s = (const float*)d_in[7];
    const float* b2s = (const float*)d_in[8];
    float* out = (float*)d_out;

    float *ench, *enc, *terms;
    __nv_bfloat16 *w2hi, *w2lo;
    cudaGetSymbolAddress((void**)&ench,  g_ench);
    cudaGetSymbolAddress((void**)&enc,   g_enc);
    cudaGetSymbolAddress((void**)&terms, g_terms);
    cudaGetSymbolAddress((void**)&w2hi,  g_w2hi);
    cudaGetSymbolAddress((void**)&w2lo,  g_w2lo);

    cudaFuncSetAttribute(terms_mma_kernel,
                         cudaFuncAttributeMaxDynamicSharedMemorySize, SMEM_TOTAL);

    w2_split_kernel<<<(DDIM * DDIM * HDIM / 4) / 256, 256>>>(
        (const float4*)W2s, (uint2*)w2hi, (uint2*)w2lo);

    gemm_nt_bias_act<<<dim3(BATCH / 64, HDIM / 64), 256>>>(
        x, We1, be1, ench, BATCH, HDIM, DDIM, 0);
    gemm_nt_bias_act<<<dim3(BATCH / 64, DDIM / 64), 256>>>(
        ench, We2, be2, enc, BATCH, DDIM, HDIM, 1);

    terms_mma_kernel<<<dim3(BATCH / 128, DDIM), 256, SMEM_TOTAL>>>(
        enc, W1s, b1s, w2hi, w2lo, terms);

    cumsum_tanh<<<(BATCH * DDIM / 4) / 256, 256>>>(terms, b2s, out);
}